// round 12
// baseline (speedup 1.0000x reference)
#include <cuda_runtime.h>
#include <cuda_fp16.h>
#include <cstdint>
#include <cstddef>

#define HG 9
#define WG 25
#define NN 225
#define BATCH 128
#define CIN 2048

#define KPAD1 1856   // 58 * 32
#define NITER1 58
#define K2 2048
#define NITER2 64
#define N1 2048
#define N2 20800
#define SPLITS1 8
#define SPLITS2 2

// ---------------- scratch ----------------
__device__ __align__(16) float g_fea_part[BATCH * 16 * NN * 8];
__device__ __align__(16) __half g_flat_h[BATCH * KPAD1];
__device__ __align__(16) __half g_hid_h[BATCH * K2];
__device__ __align__(16) float g_part[SPLITS1 * BATCH * N1];
__device__ __align__(16) float g_part2[SPLITS2 * BATCH * N2];

__device__ __forceinline__ uint32_t smem_u32(const void* p) {
    uint32_t a;
    asm("{ .reg .u64 t; cvta.to.shared.u64 t, %1; cvt.u32.u64 %0, t; }" : "=r"(a) : "l"(p));
    return a;
}

// ---------------- kernel 1: pool (frozen) ----------------
__global__ void pool_kernel(const float* __restrict__ x4, const float* __restrict__ pw) {
    int b = blockIdx.x, cc = blockIdx.y, n = threadIdx.x;
    __shared__ unsigned long long s_w[128][4];
    for (int i = threadIdx.x; i < 512; i += blockDim.x) {
        int c = i >> 2, p = i & 3;
        float w0 = pw[(p * 2) * 2048 + cc * 128 + c];
        float w1 = pw[(p * 2 + 1) * 2048 + cc * 128 + c];
        unsigned long long u;
        asm("mov.b64 %0, {%1, %2};" : "=l"(u) : "f"(w0), "f"(w1));
        s_w[c][p] = u;
    }
    __syncthreads();

    const float* xp = x4 + ((size_t)(b * CIN + cc * 128)) * NN + n;
    unsigned long long a0 = 0ull, a1 = 0ull, a2 = 0ull, a3 = 0ull;

#pragma unroll 16
    for (int c = 0; c < 128; c++) {
        float v = xp[(size_t)c * NN];
        unsigned long long vv;
        asm("mov.b64 %0, {%1, %1};" : "=l"(vv) : "f"(v));
        ulonglong2 wA = *(const ulonglong2*)&s_w[c][0];
        ulonglong2 wB = *(const ulonglong2*)&s_w[c][2];
        asm("fma.rn.f32x2 %0, %1, %2, %0;" : "+l"(a0) : "l"(vv), "l"(wA.x));
        asm("fma.rn.f32x2 %0, %1, %2, %0;" : "+l"(a1) : "l"(vv), "l"(wA.y));
        asm("fma.rn.f32x2 %0, %1, %2, %0;" : "+l"(a2) : "l"(vv), "l"(wB.x));
        asm("fma.rn.f32x2 %0, %1, %2, %0;" : "+l"(a3) : "l"(vv), "l"(wB.y));
    }
    unsigned long long* out =
        (unsigned long long*)(g_fea_part + ((size_t)((b * 16 + cc) * NN + n)) * 8);
    out[0] = a0; out[1] = a1; out[2] = a2; out[3] = a3;
}

// ---------------- kernel 2: fused GAT1 + GAT2 (frozen) ----------------
__global__ void gat_kernel(const float* __restrict__ pb,
                           const float* __restrict__ W1, const float* __restrict__ a1s,
                           const float* __restrict__ a1d, const float* __restrict__ b1,
                           const float* __restrict__ W2, const float* __restrict__ a2s,
                           const float* __restrict__ a2d, const float* __restrict__ b2) {
    extern __shared__ float sm[];
    float* h1  = sm;
    float* h2s = h1 + 64 * NN;
    float* as1 = h2s + NN * 9;
    float* as2 = as1 + NN * 5;
    float* W1s = as2 + NN;
    float* W2s = W1s + 512;

    int b = blockIdx.x, n = threadIdx.x;
    for (int i = n; i < 512; i += blockDim.x) { W1s[i] = W1[i]; W2s[i] = W2[i]; }

    float fs[8];
#pragma unroll
    for (int k = 0; k < 8; k++) fs[k] = pb[k];
#pragma unroll
    for (int cc = 0; cc < 16; cc++) {
        const float* fp = g_fea_part + ((size_t)((b * 16 + cc) * NN + n)) * 8;
#pragma unroll
        for (int k = 0; k < 8; k++) fs[k] += fp[k];
    }
    __syncthreads();

    float ad1[4];
    {
        float as[4];
#pragma unroll
        for (int h = 0; h < 4; h++) { as[h] = 0.f; ad1[h] = 0.f; }
#pragma unroll
        for (int f = 0; f < 64; f++) {
            float hv = 0.f;
#pragma unroll
            for (int k = 0; k < 8; k++) hv += fs[k] * W1s[k * 64 + f];
            h1[f * NN + n] = hv;
            int hd = f >> 4;
            as[hd] += hv * __ldg(&a1s[f]);
            ad1[hd] += hv * __ldg(&a1d[f]);
        }
#pragma unroll
        for (int h = 0; h < 4; h++) as1[n * 5 + h] = as[h];
    }
    __syncthreads();

    int i = n / WG, j = n % WG;
    int srcs[9]; float mask[9];
#pragma unroll
    for (int k = 0; k < 9; k++) {
        int di = k / 3 - 1, dj = k % 3 - 1;
        int ni = i + di, nj = j + dj;
        bool v = (ni >= 0 && ni < HG && nj >= 0 && nj < WG);
        srcs[k] = v ? ni * WG + nj : n;
        mask[k] = v ? 0.f : -1e30f;
    }

    float h2[8];
#pragma unroll
    for (int o = 0; o < 8; o++) h2[o] = 0.f;

#pragma unroll
    for (int hd = 0; hd < 4; hd++) {
        float ek[9], m = -1e30f;
#pragma unroll
        for (int k = 0; k < 9; k++) {
            float e = as1[srcs[k] * 5 + hd] + ad1[hd];
            e = e > 0.f ? e : 0.2f * e;
            e += mask[k];
            ek[k] = e; m = fmaxf(m, e);
        }
        float s = 0.f;
#pragma unroll
        for (int k = 0; k < 9; k++) { ek[k] = __expf(ek[k] - m); s += ek[k]; }
        float inv = 1.f / s;

        float acc[16];
#pragma unroll
        for (int d = 0; d < 16; d++) acc[d] = 0.f;
#pragma unroll
        for (int k = 0; k < 9; k++) {
            float w = ek[k] * inv;
            const float* hp = &h1[(hd * 16) * NN + srcs[k]];
#pragma unroll
            for (int d = 0; d < 16; d++) acc[d] += w * hp[d * NN];
        }
#pragma unroll
        for (int d = 0; d < 16; d++) {
            int f = hd * 16 + d;
            float x1 = fmaxf(acc[d] + __ldg(&b1[f]), 0.f);
#pragma unroll
            for (int o = 0; o < 8; o++) h2[o] += x1 * W2s[f * 8 + o];
        }
    }

    float ad2 = 0.f;
    {
        float a = 0.f;
#pragma unroll
        for (int o = 0; o < 8; o++) {
            h2s[n * 9 + o] = h2[o];
            a   += h2[o] * __ldg(&a2s[o]);
            ad2 += h2[o] * __ldg(&a2d[o]);
        }
        as2[n] = a;
    }
    __syncthreads();

    {
        float ek[9], m = -1e30f;
#pragma unroll
        for (int k = 0; k < 9; k++) {
            float e = as2[srcs[k]] + ad2;
            e = e > 0.f ? e : 0.2f * e;
            e += mask[k];
            ek[k] = e; m = fmaxf(m, e);
        }
        float s = 0.f;
#pragma unroll
        for (int k = 0; k < 9; k++) { ek[k] = __expf(ek[k] - m); s += ek[k]; }
        float inv = 1.f / s;

        float acc2[8];
#pragma unroll
        for (int o = 0; o < 8; o++) acc2[o] = 0.f;
#pragma unroll
        for (int k = 0; k < 9; k++) {
            float w = ek[k] * inv;
            const float* hp = &h2s[srcs[k] * 9];
#pragma unroll
            for (int o = 0; o < 8; o++) acc2[o] += w * hp[o];
        }
        size_t base = (size_t)b * KPAD1 + n * 8;
#pragma unroll
        for (int o = 0; o < 8; o++)
            g_flat_h[base + o] = __float2half(acc2[o] + __ldg(&b2[o]));
        if (n < 56)
            g_flat_h[(size_t)b * KPAD1 + 1800 + n] = __float2half(0.f);
    }
}

// ---------------- HMMA GEMM: fp16, 128x128 tile, 4 warps m64n64, split-K ----------
#define A_STR 80
#define B_STR 272
#define STG_SZ (128 * A_STR + 32 * B_STR)               // 18944
#define OFF_A(s) ((s) * STG_SZ)
#define OFF_B(s) ((s) * STG_SZ + 128 * A_STR)
#define GEMM_SMEM (2 * STG_SZ)                          // 37888

__device__ __forceinline__ void ldm_x4(uint32_t* r, uint32_t addr) {
    asm volatile("ldmatrix.sync.aligned.m8n8.x4.shared.b16 {%0,%1,%2,%3}, [%4];"
                 : "=r"(r[0]), "=r"(r[1]), "=r"(r[2]), "=r"(r[3]) : "r"(addr));
}
__device__ __forceinline__ void ldm_x4t(uint32_t* r, uint32_t addr) {
    asm volatile("ldmatrix.sync.aligned.m8n8.x4.trans.shared.b16 {%0,%1,%2,%3}, [%4];"
                 : "=r"(r[0]), "=r"(r[1]), "=r"(r[2]), "=r"(r[3]) : "r"(addr));
}
__device__ __forceinline__ void mma16816(float* c, const uint32_t* a, uint32_t b0, uint32_t b1) {
    asm volatile("mma.sync.aligned.m16n8k16.row.col.f32.f16.f16.f32 "
                 "{%0,%1,%2,%3}, {%4,%5,%6,%7}, {%8,%9}, {%0,%1,%2,%3};"
                 : "+f"(c[0]), "+f"(c[1]), "+f"(c[2]), "+f"(c[3])
                 : "r"(a[0]), "r"(a[1]), "r"(a[2]), "r"(a[3]), "r"(b0), "r"(b1));
}

__global__ void __launch_bounds__(128, 2) mma_gemm(
    const __half* __restrict__ A, int lda,
    const float* __restrict__ B, int ldb, int Krows, int Ntot, int total_iters,
    float* __restrict__ part) {
    extern __shared__ char smc[];
    uint32_t sb = smem_u32(smc);
    int t = threadIdx.x, wid = t >> 5, lane = t & 31;
    int n0 = blockIdx.x * 128;

    int it_begin, it_count;
    {
        int sp = blockIdx.y, nsp = gridDim.y;
        int base = total_iters / nsp, rem = total_iters % nsp;
        it_count = base + (sp < rem ? 1 : 0);
        it_begin = sp * base + (sp < rem ? sp : rem);
    }

    // loader maps (128 threads)
    int arow = t;                              // A: one 64B row per thread
    int brow = t >> 2, bq = t & 3;             // B: 32 rows x 4 thread-groups

    float acc[128];
#pragma unroll
    for (int c = 0; c < 128; c++) acc[c] = 0.f;

    uint4 pa[4];
    float4 pb[8];

    auto load_regs = [&](int it_rel) {
        int k0 = (it_begin + it_rel) * 32;
        const char* ga = (const char*)(A + (size_t)arow * lda + k0);
#pragma unroll
        for (int s = 0; s < 4; s++) pa[s] = *(const uint4*)(ga + s * 16);
        int kg = k0 + brow;
        bool okk = kg < Krows;
        const float* brp = B + (size_t)kg * ldb + n0;
#pragma unroll
        for (int cc = 0; cc < 8; cc++) {
            int col = bq * 4 + cc * 16;
            bool ok = okk && (n0 + col < Ntot);
            pb[cc] = ok ? *(const float4*)(brp + col) : make_float4(0.f, 0.f, 0.f, 0.f);
        }
    };
    auto store_smem = [&](int s) {
        uint32_t ab = arow * A_STR;
#pragma unroll
        for (int q = 0; q < 4; q++)
            *(uint4*)(smc + OFF_A(s) + ab + q * 16) = pa[q];
#pragma unroll
        for (int cc = 0; cc < 8; cc++) {
            int col = bq * 4 + cc * 16;
            float4 v = pb[cc];
            union { __half h[4]; uint2 u; } uh;
            uh.h[0] = __float2half(v.x); uh.h[1] = __float2half(v.y);
            uh.h[2] = __float2half(v.z); uh.h[3] = __float2half(v.w);
            *(uint2*)(smc + OFF_B(s) + brow * B_STR + col * 2) = uh.u;
        }
    };

    load_regs(0);
    store_smem(0);
    __syncthreads();

    // 4 warps: 2M x 2N, each warp m64 x n64
    int wm = wid >> 1, wn = wid & 1;
    int m0 = wm * 64;
    int lrow = lane & 15, lsel = lane >> 4;

    for (int it = 0; it < it_count; it++) {
        int buf = it & 1;
        if (it + 1 < it_count) load_regs(it + 1);

        uint32_t aoff = (m0 + lrow) * A_STR + lsel * 16;
#pragma unroll
        for (int ks = 0; ks < 2; ks++) {
            uint32_t ah[4][4];
#pragma unroll
            for (int mh = 0; mh < 4; mh++)
                ldm_x4(ah[mh], sb + OFF_A(buf) + aoff + mh * 16 * A_STR + ks * 32);

            uint32_t boff = (ks * 16 + lrow) * B_STR + wn * 128 + lsel * 16;
            uint32_t bf[2][4];
            ldm_x4t(bf[0], sb + OFF_B(buf) + boff);
#pragma unroll
            for (int jj = 0; jj < 4; jj++) {
                int cur = jj & 1;
                if (jj < 3)
                    ldm_x4t(bf[cur ^ 1], sb + OFF_B(buf) + boff + (jj + 1) * 32);
                const uint32_t* bh = bf[cur];
#pragma unroll
                for (int mh = 0; mh < 4; mh++) {
                    mma16816(acc + ((mh * 4 + jj) * 2 + 0) * 4, ah[mh], bh[0], bh[1]);
                    mma16816(acc + ((mh * 4 + jj) * 2 + 1) * 4, ah[mh], bh[2], bh[3]);
                }
            }
        }

        if (it + 1 < it_count) store_smem(buf ^ 1);
        __syncthreads();
    }

    // epilogue: fp32 partial
    int g = lane >> 2, tg = lane & 3;
    float* dst = part + (size_t)blockIdx.y * BATCH * (size_t)Ntot;
#pragma unroll
    for (int mh = 0; mh < 4; mh++) {
#pragma unroll
        for (int jj = 0; jj < 4; jj++) {
#pragma unroll
            for (int nb = 0; nb < 2; nb++) {
                const float* a4 = acc + ((mh * 4 + jj) * 2 + nb) * 4;
                int col = n0 + wn * 64 + jj * 16 + nb * 8 + tg * 2;
                if (col >= Ntot) continue;
                int m = m0 + mh * 16 + g;
                *(float2*)(dst + (size_t)m * Ntot + col) = make_float2(a4[0], a4[1]);
                *(float2*)(dst + (size_t)(m + 8) * Ntot + col) = make_float2(a4[2], a4[3]);
            }
        }
    }
}

// ---------------- fc1 reduce: 8 partials + bias + relu -> fp16 ----------------
__global__ void reduce_kernel(const float* __restrict__ b1) {
    int slot = blockIdx.x * 256 + threadIdx.x;
    const float4* P = (const float4*)g_part;
    float4 v = P[slot];
#pragma unroll
    for (int s = 1; s < SPLITS1; s++) {
        float4 u = P[(size_t)s * (BATCH * N1 / 4) + slot];
        v.x += u.x; v.y += u.y; v.z += u.z; v.w += u.w;
    }
    int base = slot * 4, col = base & (N1 - 1);
    v.x = fmaxf(v.x + __ldg(&b1[col]), 0.f);
    v.y = fmaxf(v.y + __ldg(&b1[col + 1]), 0.f);
    v.z = fmaxf(v.z + __ldg(&b1[col + 2]), 0.f);
    v.w = fmaxf(v.w + __ldg(&b1[col + 3]), 0.f);
    union { __half h[4]; uint2 u; } uh;
    uh.h[0] = __float2half(v.x); uh.h[1] = __float2half(v.y);
    uh.h[2] = __float2half(v.z); uh.h[3] = __float2half(v.w);
    *(uint2*)(g_hid_h + base) = uh.u;
}

// ---------------- fc2 reduce: 2 partials + bias -> fp32 out ----------------
__global__ void reduce2_kernel(const float* __restrict__ b2, float* __restrict__ out) {
    int slot = blockIdx.x * 256 + threadIdx.x;
    const float4* P = (const float4*)g_part2;
    float4 v = P[slot];
    float4 u = P[(size_t)(BATCH * N2 / 4) + slot];
    v.x += u.x; v.y += u.y; v.z += u.z; v.w += u.w;
    int base = slot * 4;
    int col = base % N2;
    v.x += __ldg(&b2[col]);
    v.y += __ldg(&b2[col + 1]);
    v.z += __ldg(&b2[col + 2]);
    v.w += __ldg(&b2[col + 3]);
    *(float4*)(out + base) = v;
}

// ---------------- launcher ----------------
extern "C" void kernel_launch(void* const* d_in, const int* in_sizes, int n_in,
                              void* d_out, int out_size) {
    const float* x4     = (const float*)d_in[0];
    const float* pool_w = (const float*)d_in[1];
    const float* pool_b = (const float*)d_in[2];
    const float* g1w    = (const float*)d_in[3];
    const float* g1as   = (const float*)d_in[4];
    const float* g1ad   = (const float*)d_in[5];
    const float* g1b    = (const float*)d_in[6];
    const float* g2w    = (const float*)d_in[7];
    const float* g2as   = (const float*)d_in[8];
    const float* g2ad   = (const float*)d_in[9];
    const float* g2b    = (const float*)d_in[10];
    const float* w1     = (const float*)d_in[11];
    const float* b1     = (const float*)d_in[12];
    const float* w2     = (const float*)d_in[13];
    const float* b2     = (const float*)d_in[14];
    float* out = (float*)d_out;

    const int gat_smem = (64 * NN + NN * 9 + NN * 5 + NN + 1024) * (int)sizeof(float);
    cudaFuncSetAttribute(gat_kernel, cudaFuncAttributeMaxDynamicSharedMemorySize, gat_smem);
    cudaFuncSetAttribute(mma_gemm, cudaFuncAttributeMaxDynamicSharedMemorySize, GEMM_SMEM);

    __half *fh, *hh;
    float *p1, *p2;
    cudaGetSymbolAddress((void**)&fh, g_flat_h);
    cudaGetSymbolAddress((void**)&hh, g_hid_h);
    cudaGetSymbolAddress((void**)&p1, g_part);
    cudaGetSymbolAddress((void**)&p2, g_part2);

    pool_kernel<<<dim3(128, 16), 225>>>(x4, pool_w);
    gat_kernel<<<128, 225, gat_smem>>>(pool_b, g1w, g1as, g1ad, g1b, g2w, g2as, g2ad, g2b);
    mma_gemm<<<dim3(N1 / 128, SPLITS1), 128, GEMM_SMEM>>>(
        fh, KPAD1, w1, N1, 1800, N1, NITER1, p1);
    reduce_kernel<<<BATCH * N1 / 1024, 256>>>(b1);
    mma_gemm<<<dim3((N2 + 127) / 128, SPLITS2), 128, GEMM_SMEM>>>(
        hh, K2, w2, N2, K2, N2, NITER2, p2);
    reduce2_kernel<<<BATCH * N2 / 1024, 256>>>(b2, out);
}

// round 13
// speedup vs baseline: 1.0880x; 1.0880x over previous
#include <cuda_runtime.h>
#include <cuda_fp16.h>
#include <cstdint>
#include <cstddef>

#define HG 9
#define WG 25
#define NN 225
#define BATCH 128
#define CIN 2048

#define KPAD1 1856   // 29 * 64
#define NITER1 29
#define K2 2048
#define NITER2 32
#define N1 2048
#define N2 20800
#define SPLITS1 8
#define SPLITS2 2

// ---------------- scratch ----------------
__device__ __align__(16) float g_fea_part[BATCH * 8 * NN * 8];
__device__ __align__(16) __half g_flat_h[BATCH * KPAD1];
__device__ __align__(16) __half g_hid_h[BATCH * K2];
__device__ __align__(16) float g_part[SPLITS1 * BATCH * N1];
__device__ __align__(16) float g_part2[SPLITS2 * BATCH * N2];

__device__ __forceinline__ uint32_t smem_u32(const void* p) {
    uint32_t a;
    asm("{ .reg .u64 t; cvta.to.shared.u64 t, %1; cvt.u32.u64 %0, t; }" : "=r"(a) : "l"(p));
    return a;
}

// ---------------- kernel 1: pool (2048 -> 8), 256-channel blocks ----------------
__global__ void pool_kernel(const float* __restrict__ x4, const float* __restrict__ pw) {
    int b = blockIdx.x, cc = blockIdx.y, n = threadIdx.x;
    __shared__ unsigned long long s_w[256][4];
    for (int i = threadIdx.x; i < 1024; i += blockDim.x) {
        int c = i >> 2, p = i & 3;
        float w0 = pw[(p * 2) * 2048 + cc * 256 + c];
        float w1 = pw[(p * 2 + 1) * 2048 + cc * 256 + c];
        unsigned long long u;
        asm("mov.b64 %0, {%1, %2};" : "=l"(u) : "f"(w0), "f"(w1));
        s_w[c][p] = u;
    }
    __syncthreads();

    const float* xp = x4 + ((size_t)(b * CIN + cc * 256)) * NN + n;
    unsigned long long a0 = 0ull, a1 = 0ull, a2 = 0ull, a3 = 0ull;

#pragma unroll 16
    for (int c = 0; c < 256; c++) {
        float v = xp[(size_t)c * NN];
        unsigned long long vv;
        asm("mov.b64 %0, {%1, %1};" : "=l"(vv) : "f"(v));
        ulonglong2 wA = *(const ulonglong2*)&s_w[c][0];
        ulonglong2 wB = *(const ulonglong2*)&s_w[c][2];
        asm("fma.rn.f32x2 %0, %1, %2, %0;" : "+l"(a0) : "l"(vv), "l"(wA.x));
        asm("fma.rn.f32x2 %0, %1, %2, %0;" : "+l"(a1) : "l"(vv), "l"(wA.y));
        asm("fma.rn.f32x2 %0, %1, %2, %0;" : "+l"(a2) : "l"(vv), "l"(wB.x));
        asm("fma.rn.f32x2 %0, %1, %2, %0;" : "+l"(a3) : "l"(vv), "l"(wB.y));
    }
    unsigned long long* out =
        (unsigned long long*)(g_fea_part + ((size_t)((b * 8 + cc) * NN + n)) * 8);
    out[0] = a0; out[1] = a1; out[2] = a2; out[3] = a3;
}

// ---------------- kernel 2: fused GAT1 + GAT2 (frozen, 8 chunks) ----------------
__global__ void gat_kernel(const float* __restrict__ pb,
                           const float* __restrict__ W1, const float* __restrict__ a1s,
                           const float* __restrict__ a1d, const float* __restrict__ b1,
                           const float* __restrict__ W2, const float* __restrict__ a2s,
                           const float* __restrict__ a2d, const float* __restrict__ b2) {
    extern __shared__ float sm[];
    float* h1  = sm;
    float* h2s = h1 + 64 * NN;
    float* as1 = h2s + NN * 9;
    float* as2 = as1 + NN * 5;
    float* W1s = as2 + NN;
    float* W2s = W1s + 512;

    int b = blockIdx.x, n = threadIdx.x;
    for (int i = n; i < 512; i += blockDim.x) { W1s[i] = W1[i]; W2s[i] = W2[i]; }

    float fs[8];
#pragma unroll
    for (int k = 0; k < 8; k++) fs[k] = pb[k];
#pragma unroll
    for (int cc = 0; cc < 8; cc++) {
        const float* fp = g_fea_part + ((size_t)((b * 8 + cc) * NN + n)) * 8;
#pragma unroll
        for (int k = 0; k < 8; k++) fs[k] += fp[k];
    }
    __syncthreads();

    float ad1[4];
    {
        float as[4];
#pragma unroll
        for (int h = 0; h < 4; h++) { as[h] = 0.f; ad1[h] = 0.f; }
#pragma unroll
        for (int f = 0; f < 64; f++) {
            float hv = 0.f;
#pragma unroll
            for (int k = 0; k < 8; k++) hv += fs[k] * W1s[k * 64 + f];
            h1[f * NN + n] = hv;
            int hd = f >> 4;
            as[hd] += hv * __ldg(&a1s[f]);
            ad1[hd] += hv * __ldg(&a1d[f]);
        }
#pragma unroll
        for (int h = 0; h < 4; h++) as1[n * 5 + h] = as[h];
    }
    __syncthreads();

    int i = n / WG, j = n % WG;
    int srcs[9]; float mask[9];
#pragma unroll
    for (int k = 0; k < 9; k++) {
        int di = k / 3 - 1, dj = k % 3 - 1;
        int ni = i + di, nj = j + dj;
        bool v = (ni >= 0 && ni < HG && nj >= 0 && nj < WG);
        srcs[k] = v ? ni * WG + nj : n;
        mask[k] = v ? 0.f : -1e30f;
    }

    float h2[8];
#pragma unroll
    for (int o = 0; o < 8; o++) h2[o] = 0.f;

#pragma unroll
    for (int hd = 0; hd < 4; hd++) {
        float ek[9], m = -1e30f;
#pragma unroll
        for (int k = 0; k < 9; k++) {
            float e = as1[srcs[k] * 5 + hd] + ad1[hd];
            e = e > 0.f ? e : 0.2f * e;
            e += mask[k];
            ek[k] = e; m = fmaxf(m, e);
        }
        float s = 0.f;
#pragma unroll
        for (int k = 0; k < 9; k++) { ek[k] = __expf(ek[k] - m); s += ek[k]; }
        float inv = 1.f / s;

        float acc[16];
#pragma unroll
        for (int d = 0; d < 16; d++) acc[d] = 0.f;
#pragma unroll
        for (int k = 0; k < 9; k++) {
            float w = ek[k] * inv;
            const float* hp = &h1[(hd * 16) * NN + srcs[k]];
#pragma unroll
            for (int d = 0; d < 16; d++) acc[d] += w * hp[d * NN];
        }
#pragma unroll
        for (int d = 0; d < 16; d++) {
            int f = hd * 16 + d;
            float x1 = fmaxf(acc[d] + __ldg(&b1[f]), 0.f);
#pragma unroll
            for (int o = 0; o < 8; o++) h2[o] += x1 * W2s[f * 8 + o];
        }
    }

    float ad2 = 0.f;
    {
        float a = 0.f;
#pragma unroll
        for (int o = 0; o < 8; o++) {
            h2s[n * 9 + o] = h2[o];
            a   += h2[o] * __ldg(&a2s[o]);
            ad2 += h2[o] * __ldg(&a2d[o]);
        }
        as2[n] = a;
    }
    __syncthreads();

    {
        float ek[9], m = -1e30f;
#pragma unroll
        for (int k = 0; k < 9; k++) {
            float e = as2[srcs[k]] + ad2;
            e = e > 0.f ? e : 0.2f * e;
            e += mask[k];
            ek[k] = e; m = fmaxf(m, e);
        }
        float s = 0.f;
#pragma unroll
        for (int k = 0; k < 9; k++) { ek[k] = __expf(ek[k] - m); s += ek[k]; }
        float inv = 1.f / s;

        float acc2[8];
#pragma unroll
        for (int o = 0; o < 8; o++) acc2[o] = 0.f;
#pragma unroll
        for (int k = 0; k < 9; k++) {
            float w = ek[k] * inv;
            const float* hp = &h2s[srcs[k] * 9];
#pragma unroll
            for (int o = 0; o < 8; o++) acc2[o] += w * hp[o];
        }
        size_t base = (size_t)b * KPAD1 + n * 8;
#pragma unroll
        for (int o = 0; o < 8; o++)
            g_flat_h[base + o] = __float2half(acc2[o] + __ldg(&b2[o]));
        if (n < 56)
            g_flat_h[(size_t)b * KPAD1 + 1800 + n] = __float2half(0.f);
    }
}

// ---------------- HMMA GEMM: fp16, 128x128 tile, 8 warps m32n64, BK=64 -------------
// A via cp.async (fp16 direct), B fp32->fp16 through regs in 2 chunks.
#define A_STR 144
#define B_STR 272
#define STG_SZ (128 * A_STR + 64 * B_STR)               // 35840
#define OFF_A(s) ((s) * STG_SZ)
#define OFF_B(s) ((s) * STG_SZ + 128 * A_STR)
#define GEMM_SMEM (2 * STG_SZ)                          // 71680

__device__ __forceinline__ void ldm_x4(uint32_t* r, uint32_t addr) {
    asm volatile("ldmatrix.sync.aligned.m8n8.x4.shared.b16 {%0,%1,%2,%3}, [%4];"
                 : "=r"(r[0]), "=r"(r[1]), "=r"(r[2]), "=r"(r[3]) : "r"(addr));
}
__device__ __forceinline__ void ldm_x4t(uint32_t* r, uint32_t addr) {
    asm volatile("ldmatrix.sync.aligned.m8n8.x4.trans.shared.b16 {%0,%1,%2,%3}, [%4];"
                 : "=r"(r[0]), "=r"(r[1]), "=r"(r[2]), "=r"(r[3]) : "r"(addr));
}
__device__ __forceinline__ void mma16816(float* c, const uint32_t* a, uint32_t b0, uint32_t b1) {
    asm volatile("mma.sync.aligned.m16n8k16.row.col.f32.f16.f16.f32 "
                 "{%0,%1,%2,%3}, {%4,%5,%6,%7}, {%8,%9}, {%0,%1,%2,%3};"
                 : "+f"(c[0]), "+f"(c[1]), "+f"(c[2]), "+f"(c[3])
                 : "r"(a[0]), "r"(a[1]), "r"(a[2]), "r"(a[3]), "r"(b0), "r"(b1));
}
__device__ __forceinline__ void cp_async16(uint32_t dst, const void* src) {
    asm volatile("cp.async.cg.shared.global [%0], [%1], 16;" :: "r"(dst), "l"(src));
}

__global__ void __launch_bounds__(256, 2) mma_gemm(
    const __half* __restrict__ A, int lda,
    const float* __restrict__ B, int ldb, int Krows, int Ntot, int total_iters,
    float* __restrict__ part) {
    extern __shared__ char smc[];
    uint32_t sb = smem_u32(smc);
    int t = threadIdx.x, wid = t >> 5, lane = t & 31;
    int n0 = blockIdx.x * 128;

    int it_begin, it_count;
    {
        int sp = blockIdx.y, nsp = gridDim.y;
        int base = total_iters / nsp, rem = total_iters % nsp;
        it_count = base + (sp < rem ? 1 : 0);
        it_begin = sp * base + (sp < rem ? sp : rem);
    }

    int arow = t >> 1, ahalf = t & 1;          // A: 128 rows x 128B, 64B/thread
    int brow = t >> 2, bq = t & 3;             // B: 64 rows x 4 thread-groups

    float acc[64];
#pragma unroll
    for (int c = 0; c < 64; c++) acc[c] = 0.f;

    float4 pb[4];

    auto a_async = [&](int it_rel, int s) {
        int k0 = (it_begin + it_rel) * 64;
        const char* ga = (const char*)(A + (size_t)arow * lda + k0) + ahalf * 64;
        uint32_t ad = sb + OFF_A(s) + arow * A_STR + ahalf * 64;
#pragma unroll
        for (int q = 0; q < 4; q++) cp_async16(ad + q * 16, ga + q * 16);
        asm volatile("cp.async.commit_group;" ::: "memory");
    };
    auto b_load = [&](int it_rel, int half) {
        int k0 = (it_begin + it_rel) * 64;
        int kg = k0 + brow;
        bool okk = kg < Krows;
        const float* brp = B + (size_t)kg * ldb + n0;
#pragma unroll
        for (int cc = 0; cc < 4; cc++) {
            int col = bq * 4 + (half * 4 + cc) * 16;
            bool ok = okk && (n0 + col < Ntot);
            pb[cc] = ok ? *(const float4*)(brp + col) : make_float4(0.f, 0.f, 0.f, 0.f);
        }
    };
    auto b_store = [&](int s, int half) {
#pragma unroll
        for (int cc = 0; cc < 4; cc++) {
            int col = bq * 4 + (half * 4 + cc) * 16;
            float4 v = pb[cc];
            union { __half h[4]; uint2 u; } uh;
            uh.h[0] = __float2half(v.x); uh.h[1] = __float2half(v.y);
            uh.h[2] = __float2half(v.z); uh.h[3] = __float2half(v.w);
            *(uint2*)(smc + OFF_B(s) + brow * B_STR + col * 2) = uh.u;
        }
    };

    // prologue: stage 0
    a_async(0, 0);
    b_load(0, 0); b_store(0, 0);
    b_load(0, 1); b_store(0, 1);
    asm volatile("cp.async.wait_group 0;" ::: "memory");
    __syncthreads();

    int wm = wid >> 1, wn = wid & 1;
    int m0 = wm * 32;
    int lrow = lane & 15, lsel = lane >> 4;

    auto compute_ks = [&](int buf, int ks) {
        uint32_t aoff = (m0 + lrow) * A_STR + lsel * 16 + ks * 32;
        uint32_t ah[2][4];
        ldm_x4(ah[0], sb + OFF_A(buf) + aoff);
        ldm_x4(ah[1], sb + OFF_A(buf) + aoff + 16 * A_STR);
        uint32_t boff = (ks * 16 + lrow) * B_STR + wn * 128 + lsel * 16;
        uint32_t bf[2][4];
        ldm_x4t(bf[0], sb + OFF_B(buf) + boff);
#pragma unroll
        for (int jj = 0; jj < 4; jj++) {
            int cur = jj & 1;
            if (jj < 3)
                ldm_x4t(bf[cur ^ 1], sb + OFF_B(buf) + boff + (jj + 1) * 32);
            const uint32_t* bh = bf[cur];
            float* c00 = acc + ((0 * 4 + jj) * 2 + 0) * 4;
            float* c01 = acc + ((0 * 4 + jj) * 2 + 1) * 4;
            float* c10 = acc + ((1 * 4 + jj) * 2 + 0) * 4;
            float* c11 = acc + ((1 * 4 + jj) * 2 + 1) * 4;
            mma16816(c00, ah[0], bh[0], bh[1]);
            mma16816(c01, ah[0], bh[2], bh[3]);
            mma16816(c10, ah[1], bh[0], bh[1]);
            mma16816(c11, ah[1], bh[2], bh[3]);
        }
    };

    for (int it = 0; it < it_count; it++) {
        int buf = it & 1;
        bool nxt = (it + 1 < it_count);
        if (nxt) { a_async(it + 1, buf ^ 1); b_load(it + 1, 0); }

        compute_ks(buf, 0);
        compute_ks(buf, 1);

        if (nxt) { b_store(buf ^ 1, 0); b_load(it + 1, 1); }

        compute_ks(buf, 2);
        compute_ks(buf, 3);

        if (nxt) b_store(buf ^ 1, 1);
        asm volatile("cp.async.wait_group 0;" ::: "memory");
        __syncthreads();
    }

    // epilogue: fp32 partial
    int g = lane >> 2, tg = lane & 3;
    float* dst = part + (size_t)blockIdx.y * BATCH * (size_t)Ntot;
#pragma unroll
    for (int mh = 0; mh < 2; mh++) {
#pragma unroll
        for (int jj = 0; jj < 4; jj++) {
#pragma unroll
            for (int nb = 0; nb < 2; nb++) {
                const float* a4 = acc + ((mh * 4 + jj) * 2 + nb) * 4;
                int col = n0 + wn * 64 + jj * 16 + nb * 8 + tg * 2;
                if (col >= Ntot) continue;
                int m = m0 + mh * 16 + g;
                *(float2*)(dst + (size_t)m * Ntot + col) = make_float2(a4[0], a4[1]);
                *(float2*)(dst + (size_t)(m + 8) * Ntot + col) = make_float2(a4[2], a4[3]);
            }
        }
    }
}

// ---------------- fc1 reduce: 8 partials + bias + relu -> fp16 ----------------
__global__ void reduce_kernel(const float* __restrict__ b1) {
    int slot = blockIdx.x * 256 + threadIdx.x;
    const float4* P = (const float4*)g_part;
    float4 v = P[slot];
#pragma unroll
    for (int s = 1; s < SPLITS1; s++) {
        float4 u = P[(size_t)s * (BATCH * N1 / 4) + slot];
        v.x += u.x; v.y += u.y; v.z += u.z; v.w += u.w;
    }
    int base = slot * 4, col = base & (N1 - 1);
    v.x = fmaxf(v.x + __ldg(&b1[col]), 0.f);
    v.y = fmaxf(v.y + __ldg(&b1[col + 1]), 0.f);
    v.z = fmaxf(v.z + __ldg(&b1[col + 2]), 0.f);
    v.w = fmaxf(v.w + __ldg(&b1[col + 3]), 0.f);
    union { __half h[4]; uint2 u; } uh;
    uh.h[0] = __float2half(v.x); uh.h[1] = __float2half(v.y);
    uh.h[2] = __float2half(v.z); uh.h[3] = __float2half(v.w);
    *(uint2*)(g_hid_h + base) = uh.u;
}

// ---------------- fc2 reduce: 2 partials + bias -> fp32 out ----------------
__global__ void reduce2_kernel(const float* __restrict__ b2, float* __restrict__ out) {
    int slot = blockIdx.x * 256 + threadIdx.x;
    const float4* P = (const float4*)g_part2;
    float4 v = P[slot];
    float4 u = P[(size_t)(BATCH * N2 / 4) + slot];
    v.x += u.x; v.y += u.y; v.z += u.z; v.w += u.w;
    int base = slot * 4;
    int col = base % N2;
    v.x += __ldg(&b2[col]);
    v.y += __ldg(&b2[col + 1]);
    v.z += __ldg(&b2[col + 2]);
    v.w += __ldg(&b2[col + 3]);
    *(float4*)(out + base) = v;
}

// ---------------- launcher ----------------
extern "C" void kernel_launch(void* const* d_in, const int* in_sizes, int n_in,
                              void* d_out, int out_size) {
    const float* x4     = (const float*)d_in[0];
    const float* pool_w = (const float*)d_in[1];
    const float* pool_b = (const float*)d_in[2];
    const float* g1w    = (const float*)d_in[3];
    const float* g1as   = (const float*)d_in[4];
    const float* g1ad   = (const float*)d_in[5];
    const float* g1b    = (const float*)d_in[6];
    const float* g2w    = (const float*)d_in[7];
    const float* g2as   = (const float*)d_in[8];
    const float* g2ad   = (const float*)d_in[9];
    const float* g2b    = (const float*)d_in[10];
    const float* w1     = (const float*)d_in[11];
    const float* b1     = (const float*)d_in[12];
    const float* w2     = (const float*)d_in[13];
    const float* b2     = (const float*)d_in[14];
    float* out = (float*)d_out;

    const int gat_smem = (64 * NN + NN * 9 + NN * 5 + NN + 1024) * (int)sizeof(float);
    cudaFuncSetAttribute(gat_kernel, cudaFuncAttributeMaxDynamicSharedMemorySize, gat_smem);
    cudaFuncSetAttribute(mma_gemm, cudaFuncAttributeMaxDynamicSharedMemorySize, GEMM_SMEM);

    __half *fh, *hh;
    float *p1, *p2;
    cudaGetSymbolAddress((void**)&fh, g_flat_h);
    cudaGetSymbolAddress((void**)&hh, g_hid_h);
    cudaGetSymbolAddress((void**)&p1, g_part);
    cudaGetSymbolAddress((void**)&p2, g_part2);

    pool_kernel<<<dim3(128, 8), 225>>>(x4, pool_w);
    gat_kernel<<<128, 225, gat_smem>>>(pool_b, g1w, g1as, g1ad, g1b, g2w, g2as, g2ad, g2b);
    mma_gemm<<<dim3(N1 / 128, SPLITS1), 256, GEMM_SMEM>>>(
        fh, KPAD1, w1, N1, 1800, N1, NITER1, p1);
    reduce_kernel<<<BATCH * N1 / 1024, 256>>>(b1);
    mma_gemm<<<dim3((N2 + 127) / 128, SPLITS2), 256, GEMM_SMEM>>>(
        hh, K2, w2, N2, K2, N2, NITER2, p2);
    reduce2_kernel<<<BATCH * N2 / 1024, 256>>>(b2, out);
}